// round 2
// baseline (speedup 1.0000x reference)
#include <cuda_runtime.h>
#include <math.h>

#define CCH   64
#define HWP   3136
#define NB    128
#define MTOT  401408
#define TILE  64
#define CPI   49            // chunks per image: 3136/64
#define NCHUNK 6272         // 128*49
#define GRID1 592           // 148 SMs * 4 CTAs
#define NS_T  10

__device__ float d_gram[64 * 64];
__device__ float d_sums[64];
__device__ float d_wm[64 * 64];
__device__ float d_off[64];

__global__ void zero_scratch() {
    int i = blockIdx.x * 256 + threadIdx.x;
    if (i < 4096) d_gram[i] = 0.f;
    if (i < 64)   d_sums[i] = 0.f;
}

// ---------------------------------------------------------------------------
// Kernel 1: uncentered Gram (x x^T) + per-channel sums, one pass over X.
// ---------------------------------------------------------------------------
__global__ __launch_bounds__(256) void gram_kernel(const float* __restrict__ X) {
    __shared__ float sh[64][68];   // sh[p][c]  (column-major tile of x)
    int tid = threadIdx.x;
    int ti = tid >> 4, tj = tid & 15;

    float acc[4][4];
#pragma unroll
    for (int r = 0; r < 4; r++)
#pragma unroll
        for (int c = 0; c < 4; c++) acc[r][c] = 0.f;
    float csum = 0.f;

    for (int ch = blockIdx.x; ch < NCHUNK; ch += GRID1) {
        int b  = ch / CPI;
        int pc = (ch - b * CPI) * TILE;
        const float* base = X + (b * CCH) * HWP + pc;

        // load 64 channels x 64 cols, transpose into sh[p][c]
#pragma unroll
        for (int i = 0; i < 4; i++) {
            int f = tid + i * 256;       // 0..1023
            int c = f >> 4;              // channel
            int q = f & 15;              // float4 index along p
            float4 v = *(const float4*)(base + c * HWP + q * 4);
            sh[q * 4 + 0][c] = v.x;
            sh[q * 4 + 1][c] = v.y;
            sh[q * 4 + 2][c] = v.z;
            sh[q * 4 + 3][c] = v.w;
        }
        __syncthreads();

        // per-channel sums (threads 0..63)
        if (tid < 64) {
            float s = 0.f;
#pragma unroll 8
            for (int p = 0; p < 64; p++) s += sh[p][tid];
            csum += s;
        }

        // Gram 4x4 register tile: acc[r][c] += x[4ti+r,k] * x[4tj+c,k]
#pragma unroll 8
        for (int k = 0; k < 64; k++) {
            float4 a  = *(const float4*)&sh[k][ti * 4];
            float4 bv = *(const float4*)&sh[k][tj * 4];
            acc[0][0] += a.x * bv.x; acc[0][1] += a.x * bv.y; acc[0][2] += a.x * bv.z; acc[0][3] += a.x * bv.w;
            acc[1][0] += a.y * bv.x; acc[1][1] += a.y * bv.y; acc[1][2] += a.y * bv.z; acc[1][3] += a.y * bv.w;
            acc[2][0] += a.z * bv.x; acc[2][1] += a.z * bv.y; acc[2][2] += a.z * bv.z; acc[2][3] += a.z * bv.w;
            acc[3][0] += a.w * bv.x; acc[3][1] += a.w * bv.y; acc[3][2] += a.w * bv.z; acc[3][3] += a.w * bv.w;
        }
        __syncthreads();
    }

#pragma unroll
    for (int r = 0; r < 4; r++)
#pragma unroll
        for (int c = 0; c < 4; c++)
            atomicAdd(&d_gram[(ti * 4 + r) * 64 + tj * 4 + c], acc[r][c]);
    if (tid < 64) atomicAdd(&d_sums[tid], csum);
}

// ---------------------------------------------------------------------------
// Kernel 2: build Sigma, Newton-Schulz (10 iters) in ONE block, emit wm + off.
// ---------------------------------------------------------------------------
__device__ __forceinline__ void mm_tile(const float* __restrict__ A,
                                        const float* __restrict__ Bm,
                                        int ti, int tj, float acc[4][4]) {
#pragma unroll
    for (int r = 0; r < 4; r++)
#pragma unroll
        for (int c = 0; c < 4; c++) acc[r][c] = 0.f;
#pragma unroll 4
    for (int k4 = 0; k4 < 16; k4++) {
        float4 b0 = *(const float4*)(Bm + (k4 * 4 + 0) * 64 + tj * 4);
        float4 b1 = *(const float4*)(Bm + (k4 * 4 + 1) * 64 + tj * 4);
        float4 b2 = *(const float4*)(Bm + (k4 * 4 + 2) * 64 + tj * 4);
        float4 b3 = *(const float4*)(Bm + (k4 * 4 + 3) * 64 + tj * 4);
#pragma unroll
        for (int r = 0; r < 4; r++) {
            float4 a = *(const float4*)(A + (ti * 4 + r) * 64 + k4 * 4);
            acc[r][0] += a.x * b0.x; acc[r][1] += a.x * b0.y; acc[r][2] += a.x * b0.z; acc[r][3] += a.x * b0.w;
            acc[r][0] += a.y * b1.x; acc[r][1] += a.y * b1.y; acc[r][2] += a.y * b1.z; acc[r][3] += a.y * b1.w;
            acc[r][0] += a.z * b2.x; acc[r][1] += a.z * b2.y; acc[r][2] += a.z * b2.z; acc[r][3] += a.z * b2.w;
            acc[r][0] += a.w * b3.x; acc[r][1] += a.w * b3.y; acc[r][2] += a.w * b3.z; acc[r][3] += a.w * b3.w;
        }
    }
}

__device__ __forceinline__ void store_tile(float* __restrict__ D, int ti, int tj,
                                           const float acc[4][4]) {
#pragma unroll
    for (int r = 0; r < 4; r++)
#pragma unroll
        for (int c = 0; c < 4; c++)
            D[(ti * 4 + r) * 64 + tj * 4 + c] = acc[r][c];
}

__global__ __launch_bounds__(256) void ns_kernel(const float* __restrict__ beta) {
    __shared__ float B0[64 * 64];  // P
    __shared__ float B1[64 * 64];  // Sigma_N
    __shared__ float B2[64 * 64];  // temp
    int tid = threadIdx.x;
    int ti = tid >> 4, tj = tid & 15;
    const float inv_m = 1.f / (float)MTOT;

    // Sigma (with eps + fix_cov) into B1
#pragma unroll
    for (int r = 0; r < 4; r++) {
        int i = ti * 4 + r;
        float mi = d_sums[i] * inv_m;
#pragma unroll
        for (int c = 0; c < 4; c++) {
            int j = tj * 4 + c;
            float mj = d_sums[j] * inv_m;
            float s = d_gram[i * 64 + j] * inv_m - mi * mj;
            if (i == j) s += 1e-5f;
            else        s *= 0.9f;
            B1[i * 64 + j] = s;
        }
    }
    __syncthreads();

    // trace
    if (tid < 32) {
        float s = B1[tid * 64 + tid] + B1[(tid + 32) * 64 + (tid + 32)];
#pragma unroll
        for (int o = 16; o > 0; o >>= 1) s += __shfl_xor_sync(0xffffffffu, s, o);
        if (tid == 0) B2[0] = s;
    }
    __syncthreads();
    float rTr = 1.f / B2[0];
    float srt = sqrtf(rTr);
    __syncthreads();

    // Sigma_N = Sigma * rTr ; P = I
#pragma unroll
    for (int r = 0; r < 4; r++) {
        int i = ti * 4 + r;
#pragma unroll
        for (int c = 0; c < 4; c++) {
            int j = tj * 4 + c;
            B1[i * 64 + j] *= rTr;
            B0[i * 64 + j] = (i == j) ? 1.f : 0.f;
        }
    }
    __syncthreads();

    float acc[4][4];
    for (int it = 0; it < NS_T; it++) {
        // B2 = P @ P
        mm_tile(B0, B0, ti, tj, acc);
        store_tile(B2, ti, tj, acc);
        __syncthreads();
        // B2 = (P@P) @ P
        mm_tile(B2, B0, ti, tj, acc);
        __syncthreads();
        store_tile(B2, ti, tj, acc);
        __syncthreads();
        // P = 1.5 P - 0.5 * P^3 @ Sigma_N
        mm_tile(B2, B1, ti, tj, acc);
#pragma unroll
        for (int r = 0; r < 4; r++)
#pragma unroll
            for (int c = 0; c < 4; c++)
                acc[r][c] = 1.5f * B0[(ti * 4 + r) * 64 + tj * 4 + c] - 0.5f * acc[r][c];
        __syncthreads();
        store_tile(B0, ti, tj, acc);
        __syncthreads();
    }

    // wm = P * sqrt(rTr)
#pragma unroll
    for (int r = 0; r < 4; r++)
#pragma unroll
        for (int c = 0; c < 4; c++)
            d_wm[(ti * 4 + r) * 64 + tj * 4 + c] =
                B0[(ti * 4 + r) * 64 + tj * 4 + c] * srt;

    // off[i] = beta[i] - sum_j wm[i][j]*mean[j]
    if (tid < 64) {
        float s = 0.f;
#pragma unroll 8
        for (int j = 0; j < 64; j++) s += B0[tid * 64 + j] * (d_sums[j] * inv_m);
        d_off[tid] = beta[tid] - srt * s;
    }
}

// ---------------------------------------------------------------------------
// Kernel 3: out = wm @ x + off  (second pass over X, writes output)
// ---------------------------------------------------------------------------
__global__ __launch_bounds__(256) void apply_kernel(const float* __restrict__ X,
                                                    float* __restrict__ out) {
    __shared__ float wsh[64 * 68];
    __shared__ float xsh[64 * 68];
    __shared__ float osh[64];
    int tid = threadIdx.x;
    int ti = tid >> 4, tj = tid & 15;

#pragma unroll
    for (int i = 0; i < 16; i++) {
        int f = tid + i * 256;
        wsh[(f >> 6) * 68 + (f & 63)] = d_wm[f];
    }
    if (tid < 64) osh[tid] = d_off[tid];
    __syncthreads();

    for (int ch = blockIdx.x; ch < NCHUNK; ch += GRID1) {
        int b  = ch / CPI;
        int pc = (ch - b * CPI) * TILE;
        const float* base  = X   + b * CCH * HWP + pc;
        float*       obase = out + b * CCH * HWP + pc;

#pragma unroll
        for (int i = 0; i < 4; i++) {
            int f = tid + i * 256;
            int c = f >> 4, q = f & 15;
            *(float4*)&xsh[c * 68 + q * 4] = *(const float4*)(base + c * HWP + q * 4);
        }
        __syncthreads();

        float acc[4][4];
#pragma unroll
        for (int r = 0; r < 4; r++) {
            float o = osh[ti * 4 + r];
#pragma unroll
            for (int c = 0; c < 4; c++) acc[r][c] = o;
        }

#pragma unroll 4
        for (int k4 = 0; k4 < 16; k4++) {
            float4 b0 = *(const float4*)&xsh[(k4 * 4 + 0) * 68 + tj * 4];
            float4 b1 = *(const float4*)&xsh[(k4 * 4 + 1) * 68 + tj * 4];
            float4 b2 = *(const float4*)&xsh[(k4 * 4 + 2) * 68 + tj * 4];
            float4 b3 = *(const float4*)&xsh[(k4 * 4 + 3) * 68 + tj * 4];
#pragma unroll
            for (int r = 0; r < 4; r++) {
                float4 a = *(const float4*)&wsh[(ti * 4 + r) * 68 + k4 * 4];
                acc[r][0] += a.x * b0.x; acc[r][1] += a.x * b0.y; acc[r][2] += a.x * b0.z; acc[r][3] += a.x * b0.w;
                acc[r][0] += a.y * b1.x; acc[r][1] += a.y * b1.y; acc[r][2] += a.y * b1.z; acc[r][3] += a.y * b1.w;
                acc[r][0] += a.z * b2.x; acc[r][1] += a.z * b2.y; acc[r][2] += a.z * b2.z; acc[r][3] += a.z * b2.w;
                acc[r][0] += a.w * b3.x; acc[r][1] += a.w * b3.y; acc[r][2] += a.w * b3.z; acc[r][3] += a.w * b3.w;
            }
        }

#pragma unroll
        for (int r = 0; r < 4; r++) {
            float4 v = make_float4(acc[r][0], acc[r][1], acc[r][2], acc[r][3]);
            *(float4*)(obase + (ti * 4 + r) * HWP + tj * 4) = v;
        }
        __syncthreads();
    }
}

extern "C" void kernel_launch(void* const* d_in, const int* in_sizes, int n_in,
                              void* d_out, int out_size) {
    (void)in_sizes; (void)n_in; (void)out_size;
    const float* X    = (const float*)d_in[0];
    const float* beta = (const float*)d_in[1];
    float* out        = (float*)d_out;

    zero_scratch<<<16, 256>>>();
    gram_kernel<<<GRID1, 256>>>(X);
    ns_kernel<<<1, 256>>>(beta);
    apply_kernel<<<GRID1, 256>>>(X, out);
}

// round 3
// speedup vs baseline: 1.0421x; 1.0421x over previous
#include <cuda_runtime.h>
#include <math.h>

#define CCH   64
#define HWP   3136
#define MTOT  401408
#define TILE  64
#define CPI   49            // chunks per image: 3136/64
#define NCHUNK 6272         // 128*49
#define GRID1 592           // 148 SMs * 4 CTAs
#define NS_T  10

typedef unsigned long long u64;

__device__ float d_gram[64 * 64];
__device__ float d_sums[64];
__device__ float d_wm[64 * 64];
__device__ float d_off[64];

// ---- packed f32x2 helpers -------------------------------------------------
__device__ __forceinline__ void fma2(u64 &acc, u64 a, u64 b) {
    asm("fma.rn.f32x2 %0, %1, %2, %0;" : "+l"(acc) : "l"(a), "l"(b));
}
__device__ __forceinline__ u64 dup2(float x) {
    u64 r;
    asm("mov.b64 %0, {%1, %1};" : "=l"(r) : "r"(__float_as_uint(x)));
    return r;
}
__device__ __forceinline__ float2 unpk(u64 v) {
    float2 f;
    asm("mov.b64 {%0, %1}, %2;" : "=f"(f.x), "=f"(f.y) : "l"(v));
    return f;
}

__global__ void zero_scratch() {
    int i = blockIdx.x * 256 + threadIdx.x;
    if (i < 4096) d_gram[i] = 0.f;
    if (i < 64)   d_sums[i] = 0.f;
}

// ---------------------------------------------------------------------------
// Kernel 1: uncentered Gram (x x^T) + per-channel sums, one pass over X.
// ---------------------------------------------------------------------------
__global__ __launch_bounds__(256) void gram_kernel(const float* __restrict__ X) {
    __shared__ __align__(16) float sh[64][68];   // sh[p][c]
    int tid = threadIdx.x;
    int ti = tid >> 4, tj = tid & 15;

    u64 acc[4][2];
#pragma unroll
    for (int r = 0; r < 4; r++) { acc[r][0] = 0ull; acc[r][1] = 0ull; }
    float csum = 0.f;

    for (int ch = blockIdx.x; ch < NCHUNK; ch += GRID1) {
        int b  = ch / CPI;
        int pc = (ch - b * CPI) * TILE;
        const float* base = X + (b * CCH) * HWP + pc;

#pragma unroll
        for (int i = 0; i < 4; i++) {
            int f = tid + i * 256;       // 0..1023
            int c = f >> 4;              // channel
            int q = f & 15;              // float4 index along p
            float4 v = *(const float4*)(base + c * HWP + q * 4);
            sh[q * 4 + 0][c] = v.x;
            sh[q * 4 + 1][c] = v.y;
            sh[q * 4 + 2][c] = v.z;
            sh[q * 4 + 3][c] = v.w;
        }
        __syncthreads();

        if (tid < 64) {
            float s = 0.f;
#pragma unroll 8
            for (int p = 0; p < 64; p++) s += sh[p][tid];
            csum += s;
        }

#pragma unroll 8
        for (int k = 0; k < 64; k++) {
            float4 a = *(const float4*)&sh[k][ti * 4];
            ulonglong2 bv = *(const ulonglong2*)&sh[k][tj * 4];
            u64 a0 = dup2(a.x), a1 = dup2(a.y), a2 = dup2(a.z), a3 = dup2(a.w);
            fma2(acc[0][0], a0, bv.x); fma2(acc[0][1], a0, bv.y);
            fma2(acc[1][0], a1, bv.x); fma2(acc[1][1], a1, bv.y);
            fma2(acc[2][0], a2, bv.x); fma2(acc[2][1], a2, bv.y);
            fma2(acc[3][0], a3, bv.x); fma2(acc[3][1], a3, bv.y);
        }
        __syncthreads();
    }

#pragma unroll
    for (int r = 0; r < 4; r++) {
        float2 lo = unpk(acc[r][0]);
        float2 hi = unpk(acc[r][1]);
        float* g = &d_gram[(ti * 4 + r) * 64 + tj * 4];
        atomicAdd(g + 0, lo.x); atomicAdd(g + 1, lo.y);
        atomicAdd(g + 2, hi.x); atomicAdd(g + 3, hi.y);
    }
    if (tid < 64) atomicAdd(&d_sums[tid], csum);
}

// ---------------------------------------------------------------------------
// Kernel 2: build Sigma, Newton-Schulz (10 iters) in ONE block.
// ---------------------------------------------------------------------------
__device__ __forceinline__ void mm_tile2(const float* __restrict__ A,
                                         const float* __restrict__ Bm,
                                         int ti, int tj, u64 acc[4][2]) {
#pragma unroll
    for (int r = 0; r < 4; r++) { acc[r][0] = 0ull; acc[r][1] = 0ull; }
#pragma unroll 4
    for (int k4 = 0; k4 < 16; k4++) {
        ulonglong2 b0 = *(const ulonglong2*)(Bm + (k4 * 4 + 0) * 64 + tj * 4);
        ulonglong2 b1 = *(const ulonglong2*)(Bm + (k4 * 4 + 1) * 64 + tj * 4);
        ulonglong2 b2 = *(const ulonglong2*)(Bm + (k4 * 4 + 2) * 64 + tj * 4);
        ulonglong2 b3 = *(const ulonglong2*)(Bm + (k4 * 4 + 3) * 64 + tj * 4);
#pragma unroll
        for (int r = 0; r < 4; r++) {
            float4 a = *(const float4*)(A + (ti * 4 + r) * 64 + k4 * 4);
            u64 a0 = dup2(a.x), a1 = dup2(a.y), a2 = dup2(a.z), a3 = dup2(a.w);
            fma2(acc[r][0], a0, b0.x); fma2(acc[r][1], a0, b0.y);
            fma2(acc[r][0], a1, b1.x); fma2(acc[r][1], a1, b1.y);
            fma2(acc[r][0], a2, b2.x); fma2(acc[r][1], a2, b2.y);
            fma2(acc[r][0], a3, b3.x); fma2(acc[r][1], a3, b3.y);
        }
    }
}

__device__ __forceinline__ void store_tile2(float* __restrict__ D, int ti, int tj,
                                            u64 acc[4][2]) {
#pragma unroll
    for (int r = 0; r < 4; r++) {
        float2 lo = unpk(acc[r][0]);
        float2 hi = unpk(acc[r][1]);
        float4 v = make_float4(lo.x, lo.y, hi.x, hi.y);
        *(float4*)&D[(ti * 4 + r) * 64 + tj * 4] = v;
    }
}

__global__ __launch_bounds__(256) void ns_kernel(const float* __restrict__ beta) {
    __shared__ __align__(16) float B0[64 * 64];  // P
    __shared__ __align__(16) float B1[64 * 64];  // Sigma_N
    __shared__ __align__(16) float B2[64 * 64];  // temp
    int tid = threadIdx.x;
    int ti = tid >> 4, tj = tid & 15;
    const float inv_m = 1.f / (float)MTOT;

#pragma unroll
    for (int r = 0; r < 4; r++) {
        int i = ti * 4 + r;
        float mi = d_sums[i] * inv_m;
#pragma unroll
        for (int c = 0; c < 4; c++) {
            int j = tj * 4 + c;
            float mj = d_sums[j] * inv_m;
            float s = d_gram[i * 64 + j] * inv_m - mi * mj;
            if (i == j) s += 1e-5f;
            else        s *= 0.9f;
            B1[i * 64 + j] = s;
        }
    }
    __syncthreads();

    if (tid < 32) {
        float s = B1[tid * 64 + tid] + B1[(tid + 32) * 64 + (tid + 32)];
#pragma unroll
        for (int o = 16; o > 0; o >>= 1) s += __shfl_xor_sync(0xffffffffu, s, o);
        if (tid == 0) B2[0] = s;
    }
    __syncthreads();
    float rTr = 1.f / B2[0];
    float srt = sqrtf(rTr);
    __syncthreads();

#pragma unroll
    for (int r = 0; r < 4; r++) {
        int i = ti * 4 + r;
#pragma unroll
        for (int c = 0; c < 4; c++) {
            int j = tj * 4 + c;
            B1[i * 64 + j] *= rTr;
            B0[i * 64 + j] = (i == j) ? 1.f : 0.f;
        }
    }
    __syncthreads();

    u64 acc[4][2];
    for (int it = 0; it < NS_T; it++) {
        mm_tile2(B0, B0, ti, tj, acc);          // B2 = P @ P
        store_tile2(B2, ti, tj, acc);
        __syncthreads();
        mm_tile2(B2, B0, ti, tj, acc);          // B2 = P^3
        __syncthreads();
        store_tile2(B2, ti, tj, acc);
        __syncthreads();
        mm_tile2(B2, B1, ti, tj, acc);          // P^3 @ Sigma_N
#pragma unroll
        for (int r = 0; r < 4; r++) {
            float2 lo = unpk(acc[r][0]);
            float2 hi = unpk(acc[r][1]);
            int base = (ti * 4 + r) * 64 + tj * 4;
            float n0 = 1.5f * B0[base + 0] - 0.5f * lo.x;
            float n1 = 1.5f * B0[base + 1] - 0.5f * lo.y;
            float n2 = 1.5f * B0[base + 2] - 0.5f * hi.x;
            float n3 = 1.5f * B0[base + 3] - 0.5f * hi.y;
            __syncthreads();
            B0[base + 0] = n0; B0[base + 1] = n1;
            B0[base + 2] = n2; B0[base + 3] = n3;
        }
        __syncthreads();
    }

#pragma unroll
    for (int r = 0; r < 4; r++)
#pragma unroll
        for (int c = 0; c < 4; c++)
            d_wm[(ti * 4 + r) * 64 + tj * 4 + c] =
                B0[(ti * 4 + r) * 64 + tj * 4 + c] * srt;

    if (tid < 64) {
        float s = 0.f;
#pragma unroll 8
        for (int j = 0; j < 64; j++) s += B0[tid * 64 + j] * (d_sums[j] * inv_m);
        d_off[tid] = beta[tid] - srt * s;
    }
}

// ---------------------------------------------------------------------------
// Kernel 3: out = wm @ x + off
// ---------------------------------------------------------------------------
__global__ __launch_bounds__(256) void apply_kernel(const float* __restrict__ X,
                                                    float* __restrict__ out) {
    __shared__ __align__(16) float wsh[64 * 68];
    __shared__ __align__(16) float xsh[64 * 68];
    __shared__ float osh[64];
    int tid = threadIdx.x;
    int ti = tid >> 4, tj = tid & 15;

#pragma unroll
    for (int i = 0; i < 16; i++) {
        int f = tid + i * 256;
        wsh[(f >> 6) * 68 + (f & 63)] = d_wm[f];
    }
    if (tid < 64) osh[tid] = d_off[tid];
    __syncthreads();

    for (int ch = blockIdx.x; ch < NCHUNK; ch += GRID1) {
        int b  = ch / CPI;
        int pc = (ch - b * CPI) * TILE;
        const float* base  = X   + b * CCH * HWP + pc;
        float*       obase = out + b * CCH * HWP + pc;

#pragma unroll
        for (int i = 0; i < 4; i++) {
            int f = tid + i * 256;
            int c = f >> 4, q = f & 15;
            *(float4*)&xsh[c * 68 + q * 4] = *(const float4*)(base + c * HWP + q * 4);
        }
        __syncthreads();

        u64 acc[4][2];
#pragma unroll
        for (int r = 0; r < 4; r++) {
            u64 o = dup2(osh[ti * 4 + r]);
            acc[r][0] = o; acc[r][1] = o;
        }

#pragma unroll 4
        for (int k4 = 0; k4 < 16; k4++) {
            ulonglong2 b0 = *(const ulonglong2*)&xsh[(k4 * 4 + 0) * 68 + tj * 4];
            ulonglong2 b1 = *(const ulonglong2*)&xsh[(k4 * 4 + 1) * 68 + tj * 4];
            ulonglong2 b2 = *(const ulonglong2*)&xsh[(k4 * 4 + 2) * 68 + tj * 4];
            ulonglong2 b3 = *(const ulonglong2*)&xsh[(k4 * 4 + 3) * 68 + tj * 4];
#pragma unroll
            for (int r = 0; r < 4; r++) {
                float4 a = *(const float4*)&wsh[(ti * 4 + r) * 68 + k4 * 4];
                u64 a0 = dup2(a.x), a1 = dup2(a.y), a2 = dup2(a.z), a3 = dup2(a.w);
                fma2(acc[r][0], a0, b0.x); fma2(acc[r][1], a0, b0.y);
                fma2(acc[r][0], a1, b1.x); fma2(acc[r][1], a1, b1.y);
                fma2(acc[r][0], a2, b2.x); fma2(acc[r][1], a2, b2.y);
                fma2(acc[r][0], a3, b3.x); fma2(acc[r][1], a3, b3.y);
            }
        }

#pragma unroll
        for (int r = 0; r < 4; r++) {
            float2 lo = unpk(acc[r][0]);
            float2 hi = unpk(acc[r][1]);
            float4 v = make_float4(lo.x, lo.y, hi.x, hi.y);
            *(float4*)(obase + (ti * 4 + r) * HWP + tj * 4) = v;
        }
        __syncthreads();
    }
}

extern "C" void kernel_launch(void* const* d_in, const int* in_sizes, int n_in,
                              void* d_out, int out_size) {
    (void)in_sizes; (void)n_in; (void)out_size;
    const float* X    = (const float*)d_in[0];
    const float* beta = (const float*)d_in[1];
    float* out        = (float*)d_out;

    zero_scratch<<<16, 256>>>();
    gram_kernel<<<GRID1, 256>>>(X);
    ns_kernel<<<1, 256>>>(beta);
    apply_kernel<<<GRID1, 256>>>(X, out);
}

// round 4
// speedup vs baseline: 1.1370x; 1.0911x over previous
#include <cuda_runtime.h>
#include <math.h>

#define CCH    64
#define HWP    3136
#define MTOT   401408
#define CPI    49            // chunks per image: 3136/64
#define NCHUNK 6272          // 128*49
#define NQUAD  1568          // NCHUNK/4
#define GRIDG  148           // gram: 1 CTA/SM
#define GRIDA  296           // apply: 2 CTA/SM
#define NS_T   10
#define PIT    260           // x-tile pitch (floats): 16B aligned, 4-bank row rotation

typedef unsigned long long u64;

__device__ float d_gram[64 * 64];
__device__ float d_sums[64];
__device__ float d_wm[64 * 64];
__device__ float d_off[64];

// ---- packed f32x2 helpers -------------------------------------------------
__device__ __forceinline__ void fma2(u64 &acc, u64 a, u64 b) {
    asm("fma.rn.f32x2 %0, %1, %2, %0;" : "+l"(acc) : "l"(a), "l"(b));
}
__device__ __forceinline__ u64 dup2(float x) {
    u64 r;
    asm("mov.b64 %0, {%1, %1};" : "=l"(r) : "r"(__float_as_uint(x)));
    return r;
}
__device__ __forceinline__ float2 unpk(u64 v) {
    float2 f;
    asm("mov.b64 {%0, %1}, %2;" : "=f"(f.x), "=f"(f.y) : "l"(v));
    return f;
}

__global__ void zero_scratch() {
    int i = blockIdx.x * 256 + threadIdx.x;
    if (i < 4096) d_gram[i] = 0.f;
    if (i < 64)   d_sums[i] = 0.f;
}

// ---------------------------------------------------------------------------
// Kernel 1: uncentered Gram (x x^T) + per-channel sums. Dot-product form:
// 4 groups x 64 threads, each group owns one 64-col chunk. Thread tile 8x8.
// f32x2 lanes = even/odd position parity (no transpose, no dup movs).
// ---------------------------------------------------------------------------
__global__ __launch_bounds__(256) void gram_kernel(const float* __restrict__ X) {
    __shared__ __align__(16) float xsh[64 * PIT];   // [c][4*64 p], 66.5 KB
    int tid  = threadIdx.x;
    int g    = tid >> 6;        // group 0..3
    int t    = tid & 63;
    int rowg = t >> 3, colg = t & 7;
    int ibase = rowg * 8;

    u64 acc[8][8];
#pragma unroll
    for (int a = 0; a < 8; a++)
#pragma unroll
        for (int b = 0; b < 8; b++) acc[a][b] = 0ull;
    float csum = 0.f;

    for (int q = blockIdx.x; q < NQUAD; q += GRIDG) {
        int ch = q * 4 + g;
        int bb = ch / CPI;
        int pc = (ch - bb * CPI) * 64;
        const float* base = X + bb * CCH * HWP + pc;

        __syncthreads();
#pragma unroll
        for (int i = 0; i < 16; i++) {
            int f = t + 64 * i;
            int c = f >> 4, qq = f & 15;
            *(float4*)&xsh[c * PIT + g * 64 + qq * 4] =
                *(const float4*)(base + c * HWP + qq * 4);
        }
        __syncthreads();

        if (tid < 64) {
            float s = 0.f;
#pragma unroll 8
            for (int p4 = 0; p4 < 64; p4++) {
                float4 v = *(const float4*)&xsh[tid * PIT + p4 * 4];
                s += (v.x + v.y) + (v.z + v.w);
            }
            csum += s;
        }

        int poff0 = g * 64;
#pragma unroll 2
        for (int pq = 0; pq < 16; pq++) {
            int poff = poff0 + pq * 4;
            ulonglong2 A[8], Bv[8];
#pragma unroll
            for (int ii = 0; ii < 8; ii++)
                A[ii] = *(const ulonglong2*)&xsh[(ibase + ii) * PIT + poff];
#pragma unroll
            for (int jj = 0; jj < 8; jj++)
                Bv[jj] = *(const ulonglong2*)&xsh[(colg + 8 * jj) * PIT + poff];
#pragma unroll
            for (int ii = 0; ii < 8; ii++)
#pragma unroll
                for (int jj = 0; jj < 8; jj++) {
                    fma2(acc[ii][jj], A[ii].x, Bv[jj].x);
                    fma2(acc[ii][jj], A[ii].y, Bv[jj].y);
                }
        }
    }

    // stage the 4 group-partials in smem, reduce, one atomicAdd per element
    __syncthreads();
#pragma unroll
    for (int ii = 0; ii < 8; ii++)
#pragma unroll
        for (int jj = 0; jj < 8; jj++) {
            float2 f = unpk(acc[ii][jj]);
            xsh[g * 4096 + (ibase + ii) * 64 + colg + 8 * jj] = f.x + f.y;
        }
    __syncthreads();
    for (int idx = tid; idx < 4096; idx += 256) {
        float s = xsh[idx] + xsh[4096 + idx] + xsh[8192 + idx] + xsh[12288 + idx];
        atomicAdd(&d_gram[idx], s);
    }
    if (tid < 64) atomicAdd(&d_sums[tid], csum);
}

// ---------------------------------------------------------------------------
// Kernel 2: Sigma build + Newton-Schulz, 128 threads, 8x4 tiles.
// All NS matrices are symmetric => A[i][k] read as row A[k][i..] (broadcast).
// ---------------------------------------------------------------------------
__device__ __forceinline__ void mm_sym(const float* __restrict__ A,
                                       const float* __restrict__ Bm,
                                       int ibase, int jb, u64 acc[8][2]) {
#pragma unroll
    for (int ii = 0; ii < 8; ii++) { acc[ii][0] = 0ull; acc[ii][1] = 0ull; }
#pragma unroll 4
    for (int k = 0; k < 64; k++) {
        float4 a0 = *(const float4*)&A[k * 64 + ibase];
        float4 a1 = *(const float4*)&A[k * 64 + ibase + 4];
        ulonglong2 bv = *(const ulonglong2*)&Bm[k * 64 + jb];
        u64 d0 = dup2(a0.x), d1 = dup2(a0.y), d2 = dup2(a0.z), d3 = dup2(a0.w);
        u64 d4 = dup2(a1.x), d5 = dup2(a1.y), d6 = dup2(a1.z), d7 = dup2(a1.w);
        fma2(acc[0][0], d0, bv.x); fma2(acc[0][1], d0, bv.y);
        fma2(acc[1][0], d1, bv.x); fma2(acc[1][1], d1, bv.y);
        fma2(acc[2][0], d2, bv.x); fma2(acc[2][1], d2, bv.y);
        fma2(acc[3][0], d3, bv.x); fma2(acc[3][1], d3, bv.y);
        fma2(acc[4][0], d4, bv.x); fma2(acc[4][1], d4, bv.y);
        fma2(acc[5][0], d5, bv.x); fma2(acc[5][1], d5, bv.y);
        fma2(acc[6][0], d6, bv.x); fma2(acc[6][1], d6, bv.y);
        fma2(acc[7][0], d7, bv.x); fma2(acc[7][1], d7, bv.y);
    }
}

__device__ __forceinline__ void store_rows(float* __restrict__ D, int ibase, int jb,
                                           u64 acc[8][2]) {
#pragma unroll
    for (int ii = 0; ii < 8; ii++) {
        float2 l0 = unpk(acc[ii][0]);
        float2 l1 = unpk(acc[ii][1]);
        *(float4*)&D[(ibase + ii) * 64 + jb] = make_float4(l0.x, l0.y, l1.x, l1.y);
    }
}

__global__ __launch_bounds__(128) void ns_kernel(const float* __restrict__ beta) {
    __shared__ __align__(16) float B0[4096];  // P
    __shared__ __align__(16) float B1[4096];  // Sigma_N
    __shared__ __align__(16) float B2[4096];  // P^2
    __shared__ __align__(16) float B3[4096];  // P^3
    int tid   = threadIdx.x;
    int rowg  = tid >> 4, colg = tid & 15;
    int ibase = rowg * 8, jb = colg * 4;
    const float inv_m = 1.f / (float)MTOT;

    for (int idx = tid; idx < 4096; idx += 128) {
        int i = idx >> 6, j = idx & 63;
        float mi = d_sums[i] * inv_m, mj = d_sums[j] * inv_m;
        float s = d_gram[idx] * inv_m - mi * mj;
        if (i == j) s += 1e-5f;
        else        s *= 0.9f;
        B1[idx] = s;
    }
    __syncthreads();

    if (tid < 32) {
        float s = B1[tid * 64 + tid] + B1[(tid + 32) * 64 + (tid + 32)];
#pragma unroll
        for (int o = 16; o > 0; o >>= 1) s += __shfl_xor_sync(0xffffffffu, s, o);
        if (tid == 0) B2[0] = s;
    }
    __syncthreads();
    float rTr = 1.f / B2[0];
    float srt = sqrtf(rTr);
    __syncthreads();

    for (int idx = tid; idx < 4096; idx += 128) {
        int i = idx >> 6, j = idx & 63;
        B1[idx] *= rTr;
        B0[idx] = (i == j) ? 1.f : 0.f;
    }
    __syncthreads();

    u64 acc[8][2];
    for (int it = 0; it < NS_T; it++) {
        mm_sym(B0, B0, ibase, jb, acc);      // P^2
        store_rows(B2, ibase, jb, acc);
        __syncthreads();
        mm_sym(B2, B0, ibase, jb, acc);      // P^3
        store_rows(B3, ibase, jb, acc);
        __syncthreads();
        mm_sym(B3, B1, ibase, jb, acc);      // P^3 @ Sigma_N
#pragma unroll
        for (int ii = 0; ii < 8; ii++) {
            float2 l0 = unpk(acc[ii][0]);
            float2 l1 = unpk(acc[ii][1]);
            int base = (ibase + ii) * 64 + jb;
            float4 p = *(const float4*)&B0[base];
            *(float4*)&B0[base] = make_float4(1.5f * p.x - 0.5f * l0.x,
                                              1.5f * p.y - 0.5f * l0.y,
                                              1.5f * p.z - 0.5f * l1.x,
                                              1.5f * p.w - 0.5f * l1.y);
        }
        __syncthreads();
    }

#pragma unroll
    for (int ii = 0; ii < 8; ii++) {
        int base = (ibase + ii) * 64 + jb;
        float4 p = *(const float4*)&B0[base];
        *(float4*)&d_wm[base] = make_float4(p.x * srt, p.y * srt, p.z * srt, p.w * srt);
    }
    if (tid < 64) {
        float s = 0.f;
#pragma unroll 8
        for (int j = 0; j < 64; j++) s += B0[tid * 64 + j] * (d_sums[j] * inv_m);
        d_off[tid] = beta[tid] - srt * s;
    }
}

// ---------------------------------------------------------------------------
// Kernel 3: out = wm @ x + off. 8 rows x 16 cols per thread (2 float4 groups).
// wm symmetric => row-wise reads give the transpose for free.
// ---------------------------------------------------------------------------
__global__ __launch_bounds__(256) void apply_kernel(const float* __restrict__ X,
                                                    float* __restrict__ out) {
    __shared__ __align__(16) float xsh[64 * PIT];    // [k][256 p]
    __shared__ __align__(16) float wsh[64 * 68];     // [k][i]
    __shared__ float osh[64];
    int tid   = threadIdx.x;
    int rowg  = tid >> 5;        // 0..7
    int colg  = tid & 31;        // 0..31
    int ibase = rowg * 8;
    int colA  = colg * 4, colB = 128 + colg * 4;
    int offA  = colA & 63;       // col within its chunk

#pragma unroll
    for (int i = 0; i < 16; i++) {
        int f = tid + i * 256;
        wsh[(f >> 6) * 68 + (f & 63)] = d_wm[f];
    }
    if (tid < 64) osh[tid] = d_off[tid];

    for (int q = blockIdx.x; q < NQUAD; q += GRIDA) {
        const float* bp[4];
        float*       op[4];
#pragma unroll
        for (int cc = 0; cc < 4; cc++) {
            int ch = q * 4 + cc;
            int bb = ch / CPI;
            int p0 = (ch - bb * CPI) * 64;
            bp[cc] = X   + bb * CCH * HWP + p0;
            op[cc] = out + bb * CCH * HWP + p0;
        }
        __syncthreads();
#pragma unroll
        for (int cc = 0; cc < 4; cc++) {
#pragma unroll
            for (int i = 0; i < 4; i++) {
                int f = tid + i * 256;
                int c = f >> 4, qq = f & 15;
                *(float4*)&xsh[c * PIT + cc * 64 + qq * 4] =
                    *(const float4*)(bp[cc] + c * HWP + qq * 4);
            }
        }
        __syncthreads();

        u64 acc[8][4];
#pragma unroll
        for (int ii = 0; ii < 8; ii++) {
            u64 o = dup2(osh[ibase + ii]);
            acc[ii][0] = o; acc[ii][1] = o; acc[ii][2] = o; acc[ii][3] = o;
        }

#pragma unroll 8
        for (int k = 0; k < 64; k++) {
            ulonglong2 b0 = *(const ulonglong2*)&xsh[k * PIT + colA];
            ulonglong2 b1 = *(const ulonglong2*)&xsh[k * PIT + colB];
            float4 a0 = *(const float4*)&wsh[k * 68 + ibase];
            float4 a1 = *(const float4*)&wsh[k * 68 + ibase + 4];
            u64 d0 = dup2(a0.x), d1 = dup2(a0.y), d2 = dup2(a0.z), d3 = dup2(a0.w);
            u64 d4 = dup2(a1.x), d5 = dup2(a1.y), d6 = dup2(a1.z), d7 = dup2(a1.w);
            fma2(acc[0][0], d0, b0.x); fma2(acc[0][1], d0, b0.y);
            fma2(acc[0][2], d0, b1.x); fma2(acc[0][3], d0, b1.y);
            fma2(acc[1][0], d1, b0.x); fma2(acc[1][1], d1, b0.y);
            fma2(acc[1][2], d1, b1.x); fma2(acc[1][3], d1, b1.y);
            fma2(acc[2][0], d2, b0.x); fma2(acc[2][1], d2, b0.y);
            fma2(acc[2][2], d2, b1.x); fma2(acc[2][3], d2, b1.y);
            fma2(acc[3][0], d3, b0.x); fma2(acc[3][1], d3, b0.y);
            fma2(acc[3][2], d3, b1.x); fma2(acc[3][3], d3, b1.y);
            fma2(acc[4][0], d4, b0.x); fma2(acc[4][1], d4, b0.y);
            fma2(acc[4][2], d4, b1.x); fma2(acc[4][3], d4, b1.y);
            fma2(acc[5][0], d5, b0.x); fma2(acc[5][1], d5, b0.y);
            fma2(acc[5][2], d5, b1.x); fma2(acc[5][3], d5, b1.y);
            fma2(acc[6][0], d6, b0.x); fma2(acc[6][1], d6, b0.y);
            fma2(acc[6][2], d6, b1.x); fma2(acc[6][3], d6, b1.y);
            fma2(acc[7][0], d7, b0.x); fma2(acc[7][1], d7, b0.y);
            fma2(acc[7][2], d7, b1.x); fma2(acc[7][3], d7, b1.y);
        }

        float* obA = (colg < 16) ? op[0] : op[1];
        float* obB = (colg < 16) ? op[2] : op[3];
#pragma unroll
        for (int ii = 0; ii < 8; ii++) {
            float2 l0 = unpk(acc[ii][0]);
            float2 l1 = unpk(acc[ii][1]);
            *(float4*)(obA + (ibase + ii) * HWP + offA) =
                make_float4(l0.x, l0.y, l1.x, l1.y);
            float2 l2 = unpk(acc[ii][2]);
            float2 l3 = unpk(acc[ii][3]);
            *(float4*)(obB + (ibase + ii) * HWP + offA) =
                make_float4(l2.x, l2.y, l3.x, l3.y);
        }
    }
}

extern "C" void kernel_launch(void* const* d_in, const int* in_sizes, int n_in,
                              void* d_out, int out_size) {
    (void)in_sizes; (void)n_in; (void)out_size;
    const float* X    = (const float*)d_in[0];
    const float* beta = (const float*)d_in[1];
    float* out        = (float*)d_out;

    zero_scratch<<<16, 256>>>();
    gram_kernel<<<GRIDG, 256>>>(X);
    ns_kernel<<<1, 128>>>(beta);
    apply_kernel<<<GRIDA, 256>>>(X, out);
}

// round 5
// speedup vs baseline: 1.2265x; 1.0787x over previous
#include <cuda_runtime.h>
#include <math.h>
#include <stdint.h>

#define CCH    64
#define HWP    3136
#define MTOT   401408
#define CPI    49            // 64-col chunks per image
#define NPAIR  3136          // pairs of 64-col chunks (128 cols each)
#define GRIDB  296           // 2 CTAs/SM
#define NS_T   10
#define PITA   132           // x-tile pitch (floats)

typedef unsigned long long u64;

__device__ float d_gram[4096];
__device__ float d_sums[64];
__device__ float d_wm[4096];
__device__ float d_off[64];

// ---- packed f32x2 + cp.async helpers --------------------------------------
__device__ __forceinline__ void fma2(u64 &acc, u64 a, u64 b) {
    asm("fma.rn.f32x2 %0, %1, %2, %0;" : "+l"(acc) : "l"(a), "l"(b));
}
__device__ __forceinline__ u64 dup2(float x) {
    u64 r; asm("mov.b64 %0, {%1, %1};" : "=l"(r) : "r"(__float_as_uint(x))); return r;
}
__device__ __forceinline__ float2 unpk(u64 v) {
    float2 f; asm("mov.b64 {%0, %1}, %2;" : "=f"(f.x), "=f"(f.y) : "l"(v)); return f;
}
__device__ __forceinline__ void cpa16(uint32_t dst, const float* src) {
    asm volatile("cp.async.ca.shared.global [%0], [%1], 16;" :: "r"(dst), "l"(src));
}
__device__ __forceinline__ void cp_commit() { asm volatile("cp.async.commit_group;"); }
__device__ __forceinline__ void cp_wait1()  { asm volatile("cp.async.wait_group 1;" ::: "memory"); }
__device__ __forceinline__ void cp_wait0()  { asm volatile("cp.async.wait_group 0;" ::: "memory"); }

__global__ void zero_scratch() {
    int i = blockIdx.x * 256 + threadIdx.x;
    if (i < 4096) d_gram[i] = 0.f;
    if (i < 64)   d_sums[i] = 0.f;
}

// ---------------------------------------------------------------------------
// Kernel 1: Gram (x x^T) + channel sums. cp.async double-buffered.
// 2 groups x 128 threads; each group owns one 64-col chunk of the pair and
// computes a full 64x64 gram partial with 8x4 u64 (f32x2 over p-parity) tiles.
// Interleaved rows (rowg+8*ii) / cols (colg+16*jj) for conflict-free LDS.
// ---------------------------------------------------------------------------
__global__ __launch_bounds__(256, 2) void gram_kernel(const float* __restrict__ X) {
    __shared__ __align__(16) float xsh[2][64 * PITA];
    int tid  = threadIdx.x;
    int g    = tid >> 7;          // group 0/1
    int t    = tid & 127;
    int rowg = t >> 4;            // 0..7
    int colg = t & 15;            // 0..15

    uint32_t sb0 = (uint32_t)__cvta_generic_to_shared(&xsh[0][0]);
    uint32_t sb1 = (uint32_t)__cvta_generic_to_shared(&xsh[1][0]);

    // per-thread load slots: f = tid + 256*i, i<8 -> (c, r) with c=f>>5, r=f&31
    u64 acc[8][4];
#pragma unroll
    for (int a = 0; a < 8; a++)
#pragma unroll
        for (int b = 0; b < 4; b++) acc[a][b] = 0ull;
    float csum = 0.f;

    int q = blockIdx.x;
    // preload
    {
        int c0 = 2 * q, c1 = 2 * q + 1;
        int b0 = c0 / CPI, b1 = c1 / CPI;
        const float* bp0 = X + b0 * CCH * HWP + (c0 - b0 * CPI) * 64;
        const float* bp1 = X + b1 * CCH * HWP + (c1 - b1 * CPI) * 64;
#pragma unroll
        for (int i = 0; i < 8; i++) {
            int f = tid + 256 * i;
            int c = f >> 5, r = f & 31;
            const float* src = ((r >> 4) ? bp1 : bp0) + c * HWP + (r & 15) * 4;
            cpa16(sb0 + (c * PITA + r * 4) * 4, src);
        }
        cp_commit();
    }

    int buf = 0;
    for (; q < NPAIR; q += GRIDB) {
        int qn = q + GRIDB;
        bool pre = qn < NPAIR;
        if (pre) {
            int c0 = 2 * qn, c1 = 2 * qn + 1;
            int b0 = c0 / CPI, b1 = c1 / CPI;
            const float* bp0 = X + b0 * CCH * HWP + (c0 - b0 * CPI) * 64;
            const float* bp1 = X + b1 * CCH * HWP + (c1 - b1 * CPI) * 64;
            uint32_t db = buf ? sb0 : sb1;
#pragma unroll
            for (int i = 0; i < 8; i++) {
                int f = tid + 256 * i;
                int c = f >> 5, r = f & 31;
                const float* src = ((r >> 4) ? bp1 : bp0) + c * HWP + (r & 15) * 4;
                cpa16(db + (c * PITA + r * 4) * 4, src);
            }
            cp_commit();
            cp_wait1();
        } else {
            cp_wait0();
        }
        __syncthreads();

        const float* xb = &xsh[buf][0];
        // channel sums over this pair's 128 cols (threads 0..63)
        if (tid < 64) {
            float s = 0.f;
#pragma unroll 8
            for (int p4 = 0; p4 < 32; p4++) {
                float4 v = *(const float4*)&xb[tid * PITA + p4 * 4];
                s += (v.x + v.y) + (v.z + v.w);
            }
            csum += s;
        }

        int poff = g * 64;
#pragma unroll 2
        for (int pq = 0; pq < 16; pq++) {
            int base = poff + pq * 4;
            ulonglong2 Bv[4];
#pragma unroll
            for (int jj = 0; jj < 4; jj++)
                Bv[jj] = *(const ulonglong2*)&xb[(colg + 16 * jj) * PITA + base];
#pragma unroll
            for (int ii = 0; ii < 8; ii++) {
                ulonglong2 A = *(const ulonglong2*)&xb[(rowg + 8 * ii) * PITA + base];
#pragma unroll
                for (int jj = 0; jj < 4; jj++) {
                    fma2(acc[ii][jj], A.x, Bv[jj].x);
                    fma2(acc[ii][jj], A.y, Bv[jj].y);
                }
            }
        }
        __syncthreads();
        buf ^= 1;
    }

    // stage group partials in smem, reduce, one atomicAdd per element
    float* stage = &xsh[0][0];   // 2*4096 floats fits in buffer 0
#pragma unroll
    for (int ii = 0; ii < 8; ii++)
#pragma unroll
        for (int jj = 0; jj < 4; jj++) {
            float2 f = unpk(acc[ii][jj]);
            stage[g * 4096 + (rowg + 8 * ii) * 64 + (colg + 16 * jj)] = f.x + f.y;
        }
    __syncthreads();
    for (int idx = tid; idx < 4096; idx += 256)
        atomicAdd(&d_gram[idx], stage[idx] + stage[4096 + idx]);
    if (tid < 64) atomicAdd(&d_sums[tid], csum);
}

// ---------------------------------------------------------------------------
// Kernel 2: Sigma + Newton-Schulz, 256 threads (2 warps/SMSP), 4x4 tiles.
// Symmetric A => row reads give A^T for free (broadcast).
// ---------------------------------------------------------------------------
__device__ __forceinline__ void mm_sym(const float* __restrict__ A,
                                       const float* __restrict__ Bm,
                                       int ib, int jb, u64 acc[4][2]) {
#pragma unroll
    for (int ii = 0; ii < 4; ii++) { acc[ii][0] = 0ull; acc[ii][1] = 0ull; }
#pragma unroll 8
    for (int k = 0; k < 64; k++) {
        float4 a = *(const float4*)&A[k * 64 + ib];
        ulonglong2 bv = *(const ulonglong2*)&Bm[k * 64 + jb];
        u64 d0 = dup2(a.x), d1 = dup2(a.y), d2 = dup2(a.z), d3 = dup2(a.w);
        fma2(acc[0][0], d0, bv.x); fma2(acc[0][1], d0, bv.y);
        fma2(acc[1][0], d1, bv.x); fma2(acc[1][1], d1, bv.y);
        fma2(acc[2][0], d2, bv.x); fma2(acc[2][1], d2, bv.y);
        fma2(acc[3][0], d3, bv.x); fma2(acc[3][1], d3, bv.y);
    }
}

__device__ __forceinline__ void store4(float* __restrict__ D, int ib, int jb,
                                       u64 acc[4][2]) {
#pragma unroll
    for (int ii = 0; ii < 4; ii++) {
        float2 l0 = unpk(acc[ii][0]);
        float2 l1 = unpk(acc[ii][1]);
        *(float4*)&D[(ib + ii) * 64 + jb] = make_float4(l0.x, l0.y, l1.x, l1.y);
    }
}

__global__ __launch_bounds__(256) void ns_kernel(const float* __restrict__ beta) {
    __shared__ __align__(16) float B0[4096];  // P
    __shared__ __align__(16) float B1[4096];  // Sigma_N
    __shared__ __align__(16) float B2[4096];  // P^2
    __shared__ __align__(16) float B3[4096];  // P^3
    int tid = threadIdx.x;
    int ib = (tid >> 4) * 4;     // row base (16 groups)
    int jb = (tid & 15) * 4;     // col base (16 groups)
    const float inv_m = 1.f / (float)MTOT;

    for (int idx = tid; idx < 4096; idx += 256) {
        int i = idx >> 6, j = idx & 63;
        float mi = d_sums[i] * inv_m, mj = d_sums[j] * inv_m;
        float s = d_gram[idx] * inv_m - mi * mj;
        if (i == j) s += 1e-5f;
        else        s *= 0.9f;
        B1[idx] = s;
    }
    __syncthreads();

    if (tid < 32) {
        float s = B1[tid * 64 + tid] + B1[(tid + 32) * 64 + (tid + 32)];
#pragma unroll
        for (int o = 16; o > 0; o >>= 1) s += __shfl_xor_sync(0xffffffffu, s, o);
        if (tid == 0) B2[0] = s;
    }
    __syncthreads();
    float rTr = 1.f / B2[0];
    float srt = sqrtf(rTr);
    __syncthreads();

    for (int idx = tid; idx < 4096; idx += 256) {
        int i = idx >> 6, j = idx & 63;
        B1[idx] *= rTr;
        B0[idx] = (i == j) ? 1.f : 0.f;
    }
    __syncthreads();

    u64 acc[4][2];
    for (int it = 0; it < NS_T; it++) {
        mm_sym(B0, B0, ib, jb, acc);       // P^2
        store4(B2, ib, jb, acc);
        __syncthreads();
        mm_sym(B2, B0, ib, jb, acc);       // P^3
        store4(B3, ib, jb, acc);
        __syncthreads();
        mm_sym(B3, B1, ib, jb, acc);       // P^3 @ Sigma_N
#pragma unroll
        for (int ii = 0; ii < 4; ii++) {
            float2 l0 = unpk(acc[ii][0]);
            float2 l1 = unpk(acc[ii][1]);
            int base = (ib + ii) * 64 + jb;
            float4 p = *(const float4*)&B0[base];
            *(float4*)&B0[base] = make_float4(1.5f * p.x - 0.5f * l0.x,
                                              1.5f * p.y - 0.5f * l0.y,
                                              1.5f * p.z - 0.5f * l1.x,
                                              1.5f * p.w - 0.5f * l1.y);
        }
        __syncthreads();
    }

#pragma unroll
    for (int ii = 0; ii < 4; ii++) {
        int base = (ib + ii) * 64 + jb;
        float4 p = *(const float4*)&B0[base];
        *(float4*)&d_wm[base] = make_float4(p.x * srt, p.y * srt, p.z * srt, p.w * srt);
    }
    if (tid < 64) {
        float s = 0.f;
#pragma unroll 8
        for (int j = 0; j < 64; j++) s += B0[tid * 64 + j] * (d_sums[j] * inv_m);
        d_off[tid] = beta[tid] - srt * s;
    }
}

// ---------------------------------------------------------------------------
// Kernel 3: out = wm @ x + off. cp.async double-buffered, 8 rows x 4 cols/thr.
// ---------------------------------------------------------------------------
__global__ __launch_bounds__(256, 2) void apply_kernel(const float* __restrict__ X,
                                                       float* __restrict__ out) {
    __shared__ __align__(16) float xsh[2][64 * PITA];
    __shared__ __align__(16) float wsh[64 * 68];
    __shared__ float osh[64];
    int tid   = threadIdx.x;
    int rowg  = tid >> 5;        // 0..7
    int colg  = tid & 31;        // 0..31
    int ibase = rowg * 8;

    uint32_t sb0 = (uint32_t)__cvta_generic_to_shared(&xsh[0][0]);
    uint32_t sb1 = (uint32_t)__cvta_generic_to_shared(&xsh[1][0]);

#pragma unroll
    for (int i = 0; i < 16; i++) {
        int f = tid + i * 256;
        wsh[(f >> 6) * 68 + (f & 63)] = d_wm[f];
    }
    if (tid < 64) osh[tid] = d_off[tid];

    int q = blockIdx.x;
    {
        int c0 = 2 * q, c1 = 2 * q + 1;
        int b0 = c0 / CPI, b1 = c1 / CPI;
        const float* bp0 = X + b0 * CCH * HWP + (c0 - b0 * CPI) * 64;
        const float* bp1 = X + b1 * CCH * HWP + (c1 - b1 * CPI) * 64;
#pragma unroll
        for (int i = 0; i < 8; i++) {
            int f = tid + 256 * i;
            int c = f >> 5, r = f & 31;
            const float* src = ((r >> 4) ? bp1 : bp0) + c * HWP + (r & 15) * 4;
            cpa16(sb0 + (c * PITA + r * 4) * 4, src);
        }
        cp_commit();
    }

    int buf = 0;
    for (; q < NPAIR; q += GRIDB) {
        int c0 = 2 * q, c1 = 2 * q + 1;
        int ob0 = c0 / CPI, ob1 = c1 / CPI;
        float* op0 = out + ob0 * CCH * HWP + (c0 - ob0 * CPI) * 64;
        float* op1 = out + ob1 * CCH * HWP + (c1 - ob1 * CPI) * 64;

        int qn = q + GRIDB;
        bool pre = qn < NPAIR;
        if (pre) {
            int d0 = 2 * qn, d1 = 2 * qn + 1;
            int e0 = d0 / CPI, e1 = d1 / CPI;
            const float* bp0 = X + e0 * CCH * HWP + (d0 - e0 * CPI) * 64;
            const float* bp1 = X + e1 * CCH * HWP + (d1 - e1 * CPI) * 64;
            uint32_t db = buf ? sb0 : sb1;
#pragma unroll
            for (int i = 0; i < 8; i++) {
                int f = tid + 256 * i;
                int c = f >> 5, r = f & 31;
                const float* src = ((r >> 4) ? bp1 : bp0) + c * HWP + (r & 15) * 4;
                cpa16(db + (c * PITA + r * 4) * 4, src);
            }
            cp_commit();
            cp_wait1();
        } else {
            cp_wait0();
        }
        __syncthreads();

        const float* xb = &xsh[buf][0];
        u64 acc[8][2];
#pragma unroll
        for (int ii = 0; ii < 8; ii++) {
            u64 o = dup2(osh[ibase + ii]);
            acc[ii][0] = o; acc[ii][1] = o;
        }

#pragma unroll 4
        for (int k = 0; k < 64; k++) {
            ulonglong2 bv = *(const ulonglong2*)&xb[k * PITA + colg * 4];
            float4 a0 = *(const float4*)&wsh[k * 68 + ibase];
            float4 a1 = *(const float4*)&wsh[k * 68 + ibase + 4];
            u64 d0 = dup2(a0.x), d1 = dup2(a0.y), d2 = dup2(a0.z), d3 = dup2(a0.w);
            u64 d4 = dup2(a1.x), d5 = dup2(a1.y), d6 = dup2(a1.z), d7 = dup2(a1.w);
            fma2(acc[0][0], d0, bv.x); fma2(acc[0][1], d0, bv.y);
            fma2(acc[1][0], d1, bv.x); fma2(acc[1][1], d1, bv.y);
            fma2(acc[2][0], d2, bv.x); fma2(acc[2][1], d2, bv.y);
            fma2(acc[3][0], d3, bv.x); fma2(acc[3][1], d3, bv.y);
            fma2(acc[4][0], d4, bv.x); fma2(acc[4][1], d4, bv.y);
            fma2(acc[5][0], d5, bv.x); fma2(acc[5][1], d5, bv.y);
            fma2(acc[6][0], d6, bv.x); fma2(acc[6][1], d6, bv.y);
            fma2(acc[7][0], d7, bv.x); fma2(acc[7][1], d7, bv.y);
        }

        float* op = (colg >> 4) ? op1 : op0;
        int coff = (colg & 15) * 4;
#pragma unroll
        for (int ii = 0; ii < 8; ii++) {
            float2 l0 = unpk(acc[ii][0]);
            float2 l1 = unpk(acc[ii][1]);
            *(float4*)(op + (ibase + ii) * HWP + coff) =
                make_float4(l0.x, l0.y, l1.x, l1.y);
        }
        __syncthreads();
        buf ^= 1;
    }
}

extern "C" void kernel_launch(void* const* d_in, const int* in_sizes, int n_in,
                              void* d_out, int out_size) {
    (void)in_sizes; (void)n_in; (void)out_size;
    const float* X    = (const float*)d_in[0];
    const float* beta = (const float*)d_in[1];
    float* out        = (float*)d_out;

    zero_scratch<<<16, 256>>>();
    gram_kernel<<<GRIDB, 256>>>(X);
    ns_kernel<<<1, 256>>>(beta);
    apply_kernel<<<GRIDB, 256>>>(X, out);
}